// round 2
// baseline (speedup 1.0000x reference)
#include <cuda_runtime.h>
#include <cstdint>

#define N_NODE 50000
#define N_EDGE 800000
#define D_FEAT 64
#define DEPTH  3
#define M_TERMS 11
#define NF (N_NODE * D_FEAT)   // 3,200,000

// ---------------- scratch (device globals; no allocs allowed) ----------------
__device__ float g_ybuf[3 * NF];          // S^1 x, S^2 x, S^3 x
__device__ float g_dinv[N_NODE];          // deg accumulator, then deg^-0.5
__device__ float g_val[N_EDGE];           // normalized edge weights
__device__ float g_C[16];                 // C[L][k] combination coefficients

// ---------------- kernels ----------------
__global__ void k_zero() {
    long long i = (long long)blockIdx.x * blockDim.x + threadIdx.x;
    long long total = 3LL * NF + N_NODE;
    if (i >= total) return;
    if (i < 3LL * NF) g_ybuf[i] = 0.0f;
    else              g_dinv[i - 3LL * NF] = 0.0f;
}

__global__ void k_deg(const int* __restrict__ row) {
    int e = blockIdx.x * blockDim.x + threadIdx.x;
    if (e < N_EDGE) atomicAdd(&g_dinv[row[e]], 1.0f);
}

__global__ void k_dinv() {
    int i = blockIdx.x * blockDim.x + threadIdx.x;
    if (i >= N_NODE) return;
    float d = g_dinv[i];
    if (d < 0.5f) d += 1.0f;
    g_dinv[i] = 1.0f / sqrtf(d);
}

__global__ void k_val(const int* __restrict__ row, const int* __restrict__ col,
                      const float* __restrict__ ea) {
    int e = blockIdx.x * blockDim.x + threadIdx.x;
    if (e >= N_EDGE) return;
    g_val[e] = g_dinv[row[e]] * ea[e] * g_dinv[col[e]];
}

// SpMM: yout[row[e]] += val[e] * yin[col[e]]  (per 64-feature row)
// 16 threads per edge, float4 per thread -> 256B coalesced gather + v4 red scatter.
__global__ void k_spmm(const int* __restrict__ row, const int* __restrict__ col,
                       const float* __restrict__ yin, float* __restrict__ yout) {
    int t = blockIdx.x * blockDim.x + threadIdx.x;
    int e = t >> 4;
    if (e >= N_EDGE) return;
    int c = (t & 15) << 2;

    int r  = __ldg(&row[e]);
    int cl = __ldg(&col[e]);
    float v = __ldg(&g_val[e]);

    float4 xv = __ldg((const float4*)(yin + (size_t)cl * D_FEAT + c));
    float4 o;
    o.x = v * xv.x; o.y = v * xv.y; o.z = v * xv.z; o.w = v * xv.w;

    float* dst = yout + (size_t)r * D_FEAT + c;
    asm volatile("red.global.add.v4.f32 [%0], {%1, %2, %3, %4};"
                 :: "l"(dst), "f"(o.x), "f"(o.y), "f"(o.z), "f"(o.w)
                 : "memory");
}

// Collapse the per-m Jacobi recurrence into 4x4 coefficient matrix C[L][k]:
//   out[:,L,:] = sum_k C[L][k] * (S^k x)
__global__ void k_coef(const float* __restrict__ alphas, const float* __restrict__ w,
                       const float* __restrict__ aarr, const float* __restrict__ barr) {
    if (blockIdx.x != 0 || threadIdx.x != 0) return;
    const double l = -1.0, r = 1.0;
    double C[DEPTH + 1][DEPTH + 1];
    for (int L = 0; L <= DEPTH; L++)
        for (int k = 0; k <= DEPTH; k++) C[L][k] = 0.0;

    for (int m = 0; m < M_TERMS; m++) {
        double a = aarr[m], b = barr[m], wm = w[m];
        double P[DEPTH + 1][DEPTH + 1];
        for (int L = 0; L <= DEPTH; L++)
            for (int k = 0; k <= DEPTH; k++) P[L][k] = 0.0;
        P[0][0] = 1.0;

        double coef1 = (a - b) / 2.0 - (a + b + 2.0) / 2.0 * (l + r) / (r - l);
        double coef2 = (a + b + 2.0) / (r - l);
        double al0 = alphas[0 * M_TERMS + m];
        P[1][0] = al0 * coef1;
        P[1][1] = al0 * coef2;

        for (int L = 2; L <= DEPTH; L++) {
            double Lf = (double)L;
            double coef_l    = 2.0 * Lf * (Lf + a + b) * (2.0 * Lf - 2.0 + a + b);
            double coef_lm1_1 = (2.0 * Lf + a + b - 1.0) * (2.0 * Lf + a + b) * (2.0 * Lf + a + b - 2.0);
            double coef_lm1_2 = (2.0 * Lf + a + b - 1.0) * (a * a - b * b);
            double coef_lm2   = 2.0 * (Lf - 1.0 + a) * (Lf - 1.0 + b) * (2.0 * Lf + a + b);
            double alL   = alphas[(L - 1) * M_TERMS + m];
            double alLm1 = alphas[(L - 2) * M_TERMS + m];
            double t1 = alL * (coef_lm1_1 / coef_l);
            double t2 = alL * (coef_lm1_2 / coef_l);
            double t3 = alL * alLm1 * (coef_lm2 / coef_l);
            double t1_2 = t1 * (2.0 / (r - l));
            double t2_2 = t1 * ((r + l) / (r - l)) + t2;
            for (int k = 0; k <= L; k++) {
                double pm1 = (k > 0) ? P[L - 1][k - 1] : 0.0;
                P[L][k] = t1_2 * pm1 - t2_2 * P[L - 1][k] - t3 * P[L - 2][k];
            }
        }
        for (int L = 0; L <= DEPTH; L++)
            for (int k = 0; k <= L; k++) C[L][k] += wm * P[L][k];
    }
    for (int L = 0; L <= DEPTH; L++)
        for (int k = 0; k <= DEPTH; k++) g_C[L * 4 + k] = (float)C[L][k];
}

// Epilogue: out[n, L, d] = sum_k C[L][k] * y_k[n, d]  (y_0 = x)
__global__ void k_out(const float* __restrict__ x, float* __restrict__ out) {
    int t = blockIdx.x * blockDim.x + threadIdx.x;
    if (t >= N_NODE * 16) return;
    int n = t >> 4;
    int c = (t & 15) << 2;
    size_t off = (size_t)n * D_FEAT + c;

    float4 v0 = __ldg((const float4*)(x + off));
    float4 v1 = *(const float4*)(g_ybuf + off);
    float4 v2 = *(const float4*)(g_ybuf + (size_t)NF + off);
    float4 v3 = *(const float4*)(g_ybuf + 2ULL * NF + off);

#pragma unroll
    for (int L = 0; L <= DEPTH; L++) {
        float c0 = g_C[L * 4 + 0], c1 = g_C[L * 4 + 1];
        float c2 = g_C[L * 4 + 2], c3 = g_C[L * 4 + 3];
        float4 o;
        o.x = c0 * v0.x + c1 * v1.x + c2 * v2.x + c3 * v3.x;
        o.y = c0 * v0.y + c1 * v1.y + c2 * v2.y + c3 * v3.y;
        o.z = c0 * v0.z + c1 * v1.z + c2 * v2.z + c3 * v3.z;
        o.w = c0 * v0.w + c1 * v1.w + c2 * v2.w + c3 * v3.w;
        *(float4*)(out + (size_t)n * ((DEPTH + 1) * D_FEAT) + L * D_FEAT + c) = o;
    }
}

// ---------------- launch ----------------
extern "C" void kernel_launch(void* const* d_in, const int* in_sizes, int n_in,
                              void* d_out, int out_size) {
    const float* x      = (const float*)d_in[0];
    const int*   eidx   = (const int*)d_in[1];      // (2, N_EDGE): row then col
    const float* eattr  = (const float*)d_in[2];
    const float* alphas = (const float*)d_in[3];
    const float* w      = (const float*)d_in[4];
    const float* a_arr  = (const float*)d_in[5];
    const float* b_arr  = (const float*)d_in[6];
    float* out = (float*)d_out;

    const int* row = eidx;
    const int* col = eidx + N_EDGE;

    const int B = 256;
    long long zero_total = 3LL * NF + N_NODE;
    k_zero<<<(int)((zero_total + B - 1) / B), B>>>();
    k_deg<<<(N_EDGE + B - 1) / B, B>>>(row);
    k_dinv<<<(N_NODE + B - 1) / B, B>>>();
    k_val<<<(N_EDGE + B - 1) / B, B>>>(row, col, eattr);

    float* y1 = g_ybuf;           // device-global addresses valid in device code only;
    // use kernel-side global symbols: pass via offsets inside kernels instead.
    (void)y1;

    // SpMM chain: x -> y1 -> y2 -> y3  (pointers to __device__ globals must be
    // taken inside device code; easiest is to pass offsets via separate launches
    // using the symbol directly — here we get the address via a small trick:
    // g_ybuf decays to a device pointer when referenced in a kernel argument is
    // not allowed from host, so we use cudaGetSymbolAddress once per launch call
    // (host API, capture-safe, no allocation).)
    static float* ybuf_dev = nullptr;
    if (!ybuf_dev) cudaGetSymbolAddress((void**)&ybuf_dev, g_ybuf);

    const int spmm_blocks = (N_EDGE * 16 + B - 1) / B;   // 50000
    k_spmm<<<spmm_blocks, B>>>(row, col, x,               ybuf_dev);
    k_spmm<<<spmm_blocks, B>>>(row, col, ybuf_dev,        ybuf_dev + NF);
    k_spmm<<<spmm_blocks, B>>>(row, col, ybuf_dev + NF,   ybuf_dev + 2LL * NF);

    k_coef<<<1, 32>>>(alphas, w, a_arr, b_arr);
    k_out<<<(N_NODE * 16 + B - 1) / B, B>>>(x, out);
}

// round 3
// speedup vs baseline: 1.4349x; 1.4349x over previous
#include <cuda_runtime.h>
#include <cuda_fp16.h>
#include <cstdint>

#define N_NODE 50000
#define N_EDGE 800000
#define D_FEAT 64
#define DEPTH  3
#define M_TERMS 11
#define NF (N_NODE * D_FEAT)   // 3,200,000
#define SCAN_BS 1024
#define NBLK_SCAN ((N_NODE + SCAN_BS - 1) / SCAN_BS)   // 49

// ---------------- scratch (device globals; no allocs allowed) ----------------
__device__ float  g_y32[3 * NF];          // S^1 x, S^2 x, S^3 x   (fp32, for epilogue)
__device__ __half g_yh[3 * NF];           // fp16 copies (for next gather)
__device__ __half g_xh[NF];               // fp16 copy of x
__device__ float  g_dinv[N_NODE];
__device__ int    g_cnt[N_NODE];          // degree counts, then fill cursors
__device__ int    g_rowptr[N_NODE + 1];
__device__ int    g_part[64];
__device__ int2   g_epk[N_EDGE];          // packed (col, val-bits) in CSR order
__device__ float  g_C[16];                // C[L][k] combination coefficients

// ---------------- setup kernels ----------------
__global__ void k_init() {
    int i = blockIdx.x * blockDim.x + threadIdx.x;
    if (i < N_NODE) g_cnt[i] = 0;
}

__global__ void k_deg(const int* __restrict__ row) {
    int e = blockIdx.x * blockDim.x + threadIdx.x;
    if (e < N_EDGE) atomicAdd(&g_cnt[row[e]], 1);
}

__global__ void k_dinv() {
    int i = blockIdx.x * blockDim.x + threadIdx.x;
    if (i >= N_NODE) return;
    int cnt = g_cnt[i];
    float d = (cnt == 0) ? 1.0f : (float)cnt;
    g_dinv[i] = 1.0f / sqrtf(d);
}

// ---- 3-kernel exclusive prefix scan over g_cnt -> g_rowptr ----
__global__ void k_scan1() {
    __shared__ int sh[SCAN_BS];
    int i = blockIdx.x * SCAN_BS + threadIdx.x;
    int v = (i < N_NODE) ? g_cnt[i] : 0;
    sh[threadIdx.x] = v;
    __syncthreads();
#pragma unroll
    for (int off = 1; off < SCAN_BS; off <<= 1) {
        int t = (threadIdx.x >= off) ? sh[threadIdx.x - off] : 0;
        __syncthreads();
        sh[threadIdx.x] += t;
        __syncthreads();
    }
    if (i < N_NODE) g_rowptr[i] = sh[threadIdx.x] - v;   // exclusive
    if (threadIdx.x == SCAN_BS - 1) g_part[blockIdx.x] = sh[threadIdx.x];
}

__global__ void k_scan2() {
    __shared__ int sh[64];
    int v = (threadIdx.x < NBLK_SCAN) ? g_part[threadIdx.x] : 0;
    sh[threadIdx.x] = v;
    __syncthreads();
#pragma unroll
    for (int off = 1; off < 64; off <<= 1) {
        int t = (threadIdx.x >= off) ? sh[threadIdx.x - off] : 0;
        __syncthreads();
        sh[threadIdx.x] += t;
        __syncthreads();
    }
    g_part[threadIdx.x] = sh[threadIdx.x] - v;           // exclusive
}

__global__ void k_scan3() {
    int i = blockIdx.x * blockDim.x + threadIdx.x;
    if (i < N_NODE) {
        g_rowptr[i] += g_part[i / SCAN_BS];
        g_cnt[i] = 0;                                    // reset as fill cursor
    }
    if (i == 0) g_rowptr[N_NODE] = N_EDGE;
}

// Fill CSR: packed (col, normalized val) per edge, grouped by row.
__global__ void k_fill(const int* __restrict__ row, const int* __restrict__ col,
                       const float* __restrict__ ea) {
    int e = blockIdx.x * blockDim.x + threadIdx.x;
    if (e >= N_EDGE) return;
    int r = row[e];
    int c = col[e];
    float v = __ldg(&g_dinv[r]) * ea[e] * __ldg(&g_dinv[c]);
    int pos = g_rowptr[r] + atomicAdd(&g_cnt[r], 1);
    g_epk[pos] = make_int2(c, __float_as_int(v));
}

// Convert x -> fp16
__global__ void k_xtoh(const float* __restrict__ x) {
    int i = blockIdx.x * blockDim.x + threadIdx.x;   // over NF/4
    if (i >= NF / 4) return;
    float4 v = __ldg((const float4*)(x + (size_t)i * 4));
    __half2 h0 = __floats2half2_rn(v.x, v.y);
    __half2 h1 = __floats2half2_rn(v.z, v.w);
    *(uint2*)(g_xh + (size_t)i * 4) = make_uint2(*(uint32_t*)&h0, *(uint32_t*)&h1);
}

// ---------------- CSR SpMM: 8 threads per node, 8 feats each ----------------
// gathers fp16 (128 B per edge), accumulates fp32, dual-stores fp32 + fp16
__global__ void k_spmm(const __half* __restrict__ xin,
                       float* __restrict__ y32, __half* __restrict__ y16) {
    int t = blockIdx.x * blockDim.x + threadIdx.x;
    int n = t >> 3;
    if (n >= N_NODE) return;
    int c = (t & 7) << 3;                       // feat offset (8 halves)
    int s = __ldg(&g_rowptr[n]);
    int e = __ldg(&g_rowptr[n + 1]);

    float a0 = 0.f, a1 = 0.f, a2 = 0.f, a3 = 0.f;
    float a4 = 0.f, a5 = 0.f, a6 = 0.f, a7 = 0.f;

    for (int i = s; i < e; i++) {
        int2 pk = __ldg(&g_epk[i]);
        float v = __int_as_float(pk.y);
        uint4 raw = __ldg((const uint4*)(xin + (size_t)pk.x * D_FEAT + c));
        __half2 h0 = *(__half2*)&raw.x;
        __half2 h1 = *(__half2*)&raw.y;
        __half2 h2 = *(__half2*)&raw.z;
        __half2 h3 = *(__half2*)&raw.w;
        float2 f0 = __half22float2(h0);
        float2 f1 = __half22float2(h1);
        float2 f2 = __half22float2(h2);
        float2 f3 = __half22float2(h3);
        a0 = fmaf(v, f0.x, a0); a1 = fmaf(v, f0.y, a1);
        a2 = fmaf(v, f1.x, a2); a3 = fmaf(v, f1.y, a3);
        a4 = fmaf(v, f2.x, a4); a5 = fmaf(v, f2.y, a5);
        a6 = fmaf(v, f3.x, a6); a7 = fmaf(v, f3.y, a7);
    }

    size_t off = (size_t)n * D_FEAT + c;
    *(float4*)(y32 + off)     = make_float4(a0, a1, a2, a3);
    *(float4*)(y32 + off + 4) = make_float4(a4, a5, a6, a7);

    __half2 o0 = __floats2half2_rn(a0, a1);
    __half2 o1 = __floats2half2_rn(a2, a3);
    __half2 o2 = __floats2half2_rn(a4, a5);
    __half2 o3 = __floats2half2_rn(a6, a7);
    *(uint4*)(y16 + off) = make_uint4(*(uint32_t*)&o0, *(uint32_t*)&o1,
                                      *(uint32_t*)&o2, *(uint32_t*)&o3);
}

// ---------------- coefficient collapse (tiny, 1 thread) ----------------
__global__ void k_coef(const float* __restrict__ alphas, const float* __restrict__ w,
                       const float* __restrict__ aarr, const float* __restrict__ barr) {
    if (blockIdx.x != 0 || threadIdx.x != 0) return;
    const double l = -1.0, r = 1.0;
    double C[DEPTH + 1][DEPTH + 1];
    for (int L = 0; L <= DEPTH; L++)
        for (int k = 0; k <= DEPTH; k++) C[L][k] = 0.0;

    for (int m = 0; m < M_TERMS; m++) {
        double a = aarr[m], b = barr[m], wm = w[m];
        double P[DEPTH + 1][DEPTH + 1];
        for (int L = 0; L <= DEPTH; L++)
            for (int k = 0; k <= DEPTH; k++) P[L][k] = 0.0;
        P[0][0] = 1.0;

        double coef1 = (a - b) / 2.0 - (a + b + 2.0) / 2.0 * (l + r) / (r - l);
        double coef2 = (a + b + 2.0) / (r - l);
        double al0 = alphas[0 * M_TERMS + m];
        P[1][0] = al0 * coef1;
        P[1][1] = al0 * coef2;

        for (int L = 2; L <= DEPTH; L++) {
            double Lf = (double)L;
            double coef_l     = 2.0 * Lf * (Lf + a + b) * (2.0 * Lf - 2.0 + a + b);
            double coef_lm1_1 = (2.0 * Lf + a + b - 1.0) * (2.0 * Lf + a + b) * (2.0 * Lf + a + b - 2.0);
            double coef_lm1_2 = (2.0 * Lf + a + b - 1.0) * (a * a - b * b);
            double coef_lm2   = 2.0 * (Lf - 1.0 + a) * (Lf - 1.0 + b) * (2.0 * Lf + a + b);
            double alL   = alphas[(L - 1) * M_TERMS + m];
            double alLm1 = alphas[(L - 2) * M_TERMS + m];
            double t1 = alL * (coef_lm1_1 / coef_l);
            double t2 = alL * (coef_lm1_2 / coef_l);
            double t3 = alL * alLm1 * (coef_lm2 / coef_l);
            double t1_2 = t1 * (2.0 / (r - l));
            double t2_2 = t1 * ((r + l) / (r - l)) + t2;
            for (int k = 0; k <= L; k++) {
                double pm1 = (k > 0) ? P[L - 1][k - 1] : 0.0;
                P[L][k] = t1_2 * pm1 - t2_2 * P[L - 1][k] - t3 * P[L - 2][k];
            }
        }
        for (int L = 0; L <= DEPTH; L++)
            for (int k = 0; k <= L; k++) C[L][k] += wm * P[L][k];
    }
    for (int L = 0; L <= DEPTH; L++)
        for (int k = 0; k <= DEPTH; k++) g_C[L * 4 + k] = (float)C[L][k];
}

// ---------------- epilogue: out[n,L,d] = sum_k C[L][k] * y_k[n,d] ----------------
__global__ void k_out(const float* __restrict__ x, float* __restrict__ out) {
    int t = blockIdx.x * blockDim.x + threadIdx.x;
    if (t >= N_NODE * 16) return;
    int n = t >> 4;
    int c = (t & 15) << 2;
    size_t off = (size_t)n * D_FEAT + c;

    float4 v0 = __ldg((const float4*)(x + off));
    float4 v1 = *(const float4*)(g_y32 + off);
    float4 v2 = *(const float4*)(g_y32 + (size_t)NF + off);
    float4 v3 = *(const float4*)(g_y32 + 2ULL * NF + off);

#pragma unroll
    for (int L = 0; L <= DEPTH; L++) {
        float c0 = g_C[L * 4 + 0], c1 = g_C[L * 4 + 1];
        float c2 = g_C[L * 4 + 2], c3 = g_C[L * 4 + 3];
        float4 o;
        o.x = c0 * v0.x + c1 * v1.x + c2 * v2.x + c3 * v3.x;
        o.y = c0 * v0.y + c1 * v1.y + c2 * v2.y + c3 * v3.y;
        o.z = c0 * v0.z + c1 * v1.z + c2 * v2.z + c3 * v3.z;
        o.w = c0 * v0.w + c1 * v1.w + c2 * v2.w + c3 * v3.w;
        *(float4*)(out + (size_t)n * ((DEPTH + 1) * D_FEAT) + L * D_FEAT + c) = o;
    }
}

// ---------------- launch ----------------
extern "C" void kernel_launch(void* const* d_in, const int* in_sizes, int n_in,
                              void* d_out, int out_size) {
    const float* x      = (const float*)d_in[0];
    const int*   eidx   = (const int*)d_in[1];      // (2, N_EDGE): row then col
    const float* eattr  = (const float*)d_in[2];
    const float* alphas = (const float*)d_in[3];
    const float* w      = (const float*)d_in[4];
    const float* a_arr  = (const float*)d_in[5];
    const float* b_arr  = (const float*)d_in[6];
    float* out = (float*)d_out;

    const int* row = eidx;
    const int* col = eidx + N_EDGE;

    static float*  y32 = nullptr;
    static __half* yh  = nullptr;
    static __half* xh  = nullptr;
    if (!y32) {
        cudaGetSymbolAddress((void**)&y32, g_y32);
        cudaGetSymbolAddress((void**)&yh,  g_yh);
        cudaGetSymbolAddress((void**)&xh,  g_xh);
    }

    const int B = 256;
    k_init<<<(N_NODE + B - 1) / B, B>>>();
    k_deg <<<(N_EDGE + B - 1) / B, B>>>(row);
    k_dinv<<<(N_NODE + B - 1) / B, B>>>();
    k_scan1<<<NBLK_SCAN, SCAN_BS>>>();
    k_scan2<<<1, 64>>>();
    k_scan3<<<(N_NODE + B - 1) / B, B>>>();
    k_fill<<<(N_EDGE + B - 1) / B, B>>>(row, col, eattr);
    k_xtoh<<<(NF / 4 + B - 1) / B, B>>>(x);

    const int spmm_blocks = (N_NODE * 8 + B - 1) / B;   // 1563
    k_spmm<<<spmm_blocks, B>>>(xh,           y32,           yh);
    k_spmm<<<spmm_blocks, B>>>(yh,           y32 + NF,      yh + NF);
    k_spmm<<<spmm_blocks, B>>>(yh + NF,      y32 + 2LL*NF,  yh + 2LL*NF);

    k_coef<<<1, 32>>>(alphas, w, a_arr, b_arr);
    k_out<<<(N_NODE * 16 + B - 1) / B, B>>>(x, out);
}